// round 8
// baseline (speedup 1.0000x reference)
#include <cuda_runtime.h>

// Row-wise L1 normalization: y[b,r,:] = x[b,r,:] / max(sum(x[b,r,:]), 1e-5)
// [16, 2048, 2048] fp32. 512-thread CTA = 8 warp-pairs, each pair owns one row
// (64 lanes x 8 float4 = 2048 floats, register-resident, MLP=8).
// Eight independent rows interleave inside the CTA so each pair's
// barrier/reduce hides under the others' memory traffic.
// Pair-local sync via named barriers (bar.sync id, 64), ids 1..8.

#define ROW_LEN 2048
#define V4_PER_ROW (ROW_LEN / 4)        // 512
#define THREADS 512
#define HALF 64
#define PAIRS (THREADS / HALF)          // 8
#define V4_PER_THREAD (V4_PER_ROW / HALF)  // 8
#define N_ROWS (16 * 2048)              // 32768
#define GRID (N_ROWS / PAIRS)           // 4096

__global__ __launch_bounds__(THREADS)
void rownorm_8row_kernel(const float4* __restrict__ in, float4* __restrict__ out) {
    const int t = threadIdx.x;
    const int pair = t >> 6;            // 0..7: which row this warp-pair owns
    const int ht = t & (HALF - 1);      // 0..63 within the pair
    const int row = blockIdx.x * PAIRS + pair;
    const long long base = (long long)row * V4_PER_ROW + ht;

    // Front-batched streaming loads: 8 independent LDG.128 per thread.
    float4 v[V4_PER_THREAD];
    #pragma unroll
    for (int i = 0; i < V4_PER_THREAD; i++)
        v[i] = __ldcs(&in[base + i * HALF]);

    float s = 0.0f;
    #pragma unroll
    for (int i = 0; i < V4_PER_THREAD; i++)
        s += (v[i].x + v[i].y) + (v[i].z + v[i].w);

    // Warp reduction.
    #pragma unroll
    for (int o = 16; o > 0; o >>= 1)
        s += __shfl_xor_sync(0xffffffffu, s, o);

    // Pair-local combine of the two warps via named barrier (64 threads).
    __shared__ float ws[PAIRS * 2];     // [pair*2 + warp_in_pair]
    const int wip = (t >> 5) & 1;
    if ((t & 31) == 0) ws[pair * 2 + wip] = s;
    // Named barrier per pair: ids 1..8, 64 threads each.
    asm volatile("bar.sync %0, 64;" :: "r"(1 + pair) : "memory");

    const float inv = 1.0f / fmaxf(ws[pair * 2] + ws[pair * 2 + 1], 1e-5f);

    #pragma unroll
    for (int i = 0; i < V4_PER_THREAD; i++) {
        float4 w = v[i];
        w.x *= inv; w.y *= inv; w.z *= inv; w.w *= inv;
        __stcs(&out[base + i * HALF], w);
    }
}

extern "C" void kernel_launch(void* const* d_in, const int* in_sizes, int n_in,
                              void* d_out, int out_size) {
    const float4* in = (const float4*)d_in[0];
    float4* out = (float4*)d_out;
    rownorm_8row_kernel<<<GRID, THREADS>>>(in, out);
}

// round 9
// speedup vs baseline: 1.0099x; 1.0099x over previous
#include <cuda_runtime.h>

// Row-wise L1 normalization: y[b,r,:] = x[b,r,:] / max(sum(x[b,r,:]), 1e-5)
// [16, 2048, 2048] fp32. 128-thread CTA = 2 warp-pairs, each pair owns one row.
// Per-thread: 8 float4 (MLP=8). The two rows' phases interleave inside the CTA
// so one pair's barrier/reduce hides under the other's memory traffic.
// Pair-local sync via named barriers (bar.sync id, 64).
// Best-timed configuration (R6): 80.6 us, DRAM 81.4%, ~6.45 TB/s sustained.

#define ROW_LEN 2048
#define V4_PER_ROW (ROW_LEN / 4)        // 512
#define THREADS 128
#define HALF 64
#define V4_PER_THREAD (V4_PER_ROW / HALF)  // 8
#define N_ROWS (16 * 2048)              // 32768
#define GRID (N_ROWS / 2)               // 16384

__global__ __launch_bounds__(THREADS)
void rownorm_2row_kernel(const float4* __restrict__ in, float4* __restrict__ out) {
    const int t = threadIdx.x;
    const int half = t >> 6;            // 0 or 1: which row this warp-pair owns
    const int ht = t & (HALF - 1);      // 0..63 within the pair
    const int row = blockIdx.x * 2 + half;
    const long long base = (long long)row * V4_PER_ROW + ht;

    // Front-batched streaming loads: 8 independent LDG.128 per thread.
    float4 v[V4_PER_THREAD];
    #pragma unroll
    for (int i = 0; i < V4_PER_THREAD; i++)
        v[i] = __ldcs(&in[base + i * HALF]);

    float s = 0.0f;
    #pragma unroll
    for (int i = 0; i < V4_PER_THREAD; i++)
        s += (v[i].x + v[i].y) + (v[i].z + v[i].w);

    // Warp reduction.
    #pragma unroll
    for (int o = 16; o > 0; o >>= 1)
        s += __shfl_xor_sync(0xffffffffu, s, o);

    // Pair-local combine of the two warps via named barrier (64 threads).
    __shared__ float ws[4];             // [half*2 + warp_in_pair]
    const int wip = (t >> 5) & 1;
    if ((t & 31) == 0) ws[half * 2 + wip] = s;
    // Named barrier per pair: id 1 and 2, 64 threads each.
    asm volatile("bar.sync %0, 64;" :: "r"(1 + half) : "memory");

    const float inv = 1.0f / fmaxf(ws[half * 2] + ws[half * 2 + 1], 1e-5f);

    #pragma unroll
    for (int i = 0; i < V4_PER_THREAD; i++) {
        float4 w = v[i];
        w.x *= inv; w.y *= inv; w.z *= inv; w.w *= inv;
        __stcs(&out[base + i * HALF], w);
    }
}

extern "C" void kernel_launch(void* const* d_in, const int* in_sizes, int n_in,
                              void* d_out, int out_size) {
    const float4* in = (const float4*)d_in[0];
    float4* out = (float4*)d_out;
    rownorm_2row_kernel<<<GRID, THREADS>>>(in, out);
}